// round 1
// baseline (speedup 1.0000x reference)
#include <cuda_runtime.h>
#include <math.h>

#define NN   8192
#define FIN  128
#define FOUT 64

// Scratch (no cudaMalloc allowed) — device globals.
__device__ float g_Wh[NN * FOUT];   // 2 MB, L2-resident
__device__ float g_f1[NN];
__device__ float g_f2[NN];
__device__ float g_maxf2;

// ---------------------------------------------------------------------------
// Kernel A: Wh = h @ W   (8192x128 @ 128x64)
// grid 512, block 256. Each block: 16 rows. W staged in smem.
// ---------------------------------------------------------------------------
__global__ void __launch_bounds__(256) k_wh(const float* __restrict__ h,
                                            const float* __restrict__ W) {
    __shared__ float sW[FIN * FOUT];   // 32 KB
    int t = threadIdx.x;
    for (int q = t; q < FIN * FOUT; q += 256) sW[q] = W[q];
    __syncthreads();

    int r = t >> 6;    // 0..3
    int d = t & 63;
    #pragma unroll
    for (int rr = 0; rr < 4; rr++) {
        int i = blockIdx.x * 16 + rr * 4 + r;
        const float4* h4 = (const float4*)(h + i * FIN);
        float acc = 0.f;
        #pragma unroll
        for (int kb = 0; kb < 32; kb++) {
            float4 hv = h4[kb];   // warp-uniform broadcast load
            acc += hv.x * sW[(4 * kb + 0) * 64 + d];
            acc += hv.y * sW[(4 * kb + 1) * 64 + d];
            acc += hv.z * sW[(4 * kb + 2) * 64 + d];
            acc += hv.w * sW[(4 * kb + 3) * 64 + d];
        }
        g_Wh[i * 64 + d] = acc;
    }
}

// ---------------------------------------------------------------------------
// Kernel B: f1[i] = Wh[i]·a1, f2[i] = Wh[i]·a2.  One warp per 32 rows.
// grid 32, block 256 -> 256 warps x 32 rows = 8192.
// ---------------------------------------------------------------------------
__global__ void __launch_bounds__(256) k_f(const float* __restrict__ a) {
    int warp = blockIdx.x * 8 + (threadIdx.x >> 5);
    int lane = threadIdx.x & 31;
    float a1x = a[2 * lane], a1y = a[2 * lane + 1];
    float a2x = a[64 + 2 * lane], a2y = a[64 + 2 * lane + 1];
    for (int r = 0; r < 32; r++) {
        int i = warp * 32 + r;
        float2 v = ((const float2*)g_Wh)[i * 32 + lane];
        float p1 = v.x * a1x + v.y * a1y;
        float p2 = v.x * a2x + v.y * a2y;
        #pragma unroll
        for (int off = 16; off; off >>= 1) {
            p1 += __shfl_xor_sync(0xFFFFFFFFu, p1, off);
            p2 += __shfl_xor_sync(0xFFFFFFFFu, p2, off);
        }
        if (lane == 0) { g_f1[i] = p1; g_f2[i] = p2; }
    }
}

// ---------------------------------------------------------------------------
// Kernel C: g_maxf2 = max(f2).
// ---------------------------------------------------------------------------
__global__ void k_max() {
    __shared__ float s[256];
    float m = -INFINITY;
    for (int i = threadIdx.x; i < NN; i += 256) m = fmaxf(m, g_f2[i]);
    s[threadIdx.x] = m;
    __syncthreads();
    for (int st = 128; st; st >>= 1) {
        if (threadIdx.x < st) s[threadIdx.x] = fmaxf(s[threadIdx.x], s[threadIdx.x + st]);
        __syncthreads();
    }
    if (threadIdx.x == 0) g_maxf2 = s[0];
}

// ---------------------------------------------------------------------------
// Kernel D: streaming softmax-weighted aggregation + elu.
//   out[i] = elu( (sum_j exp(lrelu(f1_i+f2_j) - m_i) * Wh[j]) / sum_j w_ij )
// m_i = lrelu(f1_i + max f2): exact row max (lrelu monotone) -> single pass.
// grid 128 (64 rows/block), block 256.
// Thread layout for accumulation: t = dg*64 + i  (dg = d-group of 16, i = row).
// Inner product uses packed fma.rn.f32x2 (FFMA2) — 2 MACs/inst.
// ---------------------------------------------------------------------------
__global__ void __launch_bounds__(256) k_attn(float* __restrict__ out) {
    __shared__ float sWh[64 * 64];      // 16 KB, [j][d]
    __shared__ float sw[64 * 65];       // 16.6 KB, [i][j] padded
    __shared__ float sf1[64], smx[64], sf2[64], ssum[64];

    int t  = threadIdx.x;
    int i0 = blockIdx.x * 64;
    int i  = t & 63;
    int dg = t >> 6;

    if (t < 64) {
        float f1 = g_f1[i0 + t];
        sf1[t] = f1;
        float s = f1 + g_maxf2;
        smx[t] = fmaxf(s, 0.01f * s);    // lrelu(f1_i + max f2) = row max
    }

    unsigned long long acc[8];           // 16 fp32 accumulators as 8 f32x2
    #pragma unroll
    for (int q = 0; q < 8; q++) acc[q] = 0ULL;
    float sumw = 0.f;

    __syncthreads();

    for (int jc = 0; jc < 128; jc++) {
        // stage Wh chunk [64][64] + f2 chunk
        const float4* src = (const float4*)(g_Wh + jc * 64 * 64);
        float4* dst = (float4*)sWh;
        #pragma unroll
        for (int q = 0; q < 4; q++) dst[t + q * 256] = src[t + q * 256];
        if (t < 64) sf2[t] = g_f2[jc * 64 + t];
        __syncthreads();

        // compute weights w[i][j] = exp(lrelu(f1_i+f2_j) - m_i), 4096 entries
        #pragma unroll
        for (int q = 0; q < 16; q++) {
            int idx = q * 256 + t;
            int ii = idx >> 6, jj = idx & 63;
            float s = sf1[ii] + sf2[jj];
            float l = fmaxf(s, 0.01f * s);
            sw[ii * 65 + jj] = __expf(l - smx[ii]);
        }
        __syncthreads();

        // accumulate: thread (i, dg) owns 16 output dims d = dg*16 + [0..15]
        #pragma unroll 4
        for (int j = 0; j < 64; j++) {
            float w = sw[i * 65 + j];
            unsigned int wu = __float_as_uint(w);
            unsigned long long w2;
            asm("mov.b64 %0, {%1, %2};" : "=l"(w2) : "r"(wu), "r"(wu));
            const ulonglong2* vp = (const ulonglong2*)(sWh + j * 64 + dg * 16);
            #pragma unroll
            for (int q = 0; q < 4; q++) {
                ulonglong2 v = vp[q];   // warp-uniform LDS.128 broadcast
                asm("fma.rn.f32x2 %0, %1, %2, %0;" : "+l"(acc[2 * q])     : "l"(v.x), "l"(w2));
                asm("fma.rn.f32x2 %0, %1, %2, %0;" : "+l"(acc[2 * q + 1]) : "l"(v.y), "l"(w2));
            }
            if (dg == 0) sumw += w;     // warp-uniform branch (dg const per warp)
        }
        __syncthreads();
    }

    if (dg == 0) ssum[i] = sumw;
    __syncthreads();

    float inv = 1.0f / ssum[i];
    float res[16];
    #pragma unroll
    for (int q = 0; q < 8; q++) {
        float2 f;
        memcpy(&f, &acc[q], 8);
        res[2 * q]     = f.x * inv;
        res[2 * q + 1] = f.y * inv;
    }
    #pragma unroll
    for (int c = 0; c < 16; c++) {
        float x = res[c];
        res[c] = x > 0.f ? x : expm1f(x);   // elu
    }
    float4* o4 = (float4*)(out + (i0 + i) * 64 + dg * 16);
    #pragma unroll
    for (int q = 0; q < 4; q++)
        o4[q] = make_float4(res[4 * q], res[4 * q + 1], res[4 * q + 2], res[4 * q + 3]);
}

// ---------------------------------------------------------------------------
extern "C" void kernel_launch(void* const* d_in, const int* in_sizes, int n_in,
                              void* d_out, int out_size) {
    const float* h = (const float*)d_in[0];
    const float* W = (const float*)d_in[1];
    const float* a = (const float*)d_in[2];
    float* out = (float*)d_out;

    k_wh  <<<512, 256>>>(h, W);
    k_f   <<<32, 256>>>(a);
    k_max <<<1, 256>>>();
    k_attn<<<128, 256>>>(out);
}

// round 2
// speedup vs baseline: 1.0889x; 1.0889x over previous
#include <cuda_runtime.h>
#include <math.h>

#define NN   8192
#define FIN  128
#define FOUT 64

// Scratch (no cudaMalloc allowed) — device globals.
__device__ float  g_Wh[NN * FOUT];   // 2 MB, L2-resident
__device__ float  g_f1[NN];
__device__ float  g_f2[NN];
__device__ float  g_maxf2;
__device__ float4 g_JP[NN];          // (f2_j, exp(f2_j), exp(0.01*f2_j), 0)

// ---------------------------------------------------------------------------
// Kernel A: Wh = h @ W   (8192x128 @ 128x64)
// ---------------------------------------------------------------------------
__global__ void __launch_bounds__(256) k_wh(const float* __restrict__ h,
                                            const float* __restrict__ W) {
    __shared__ float sW[FIN * FOUT];   // 32 KB
    int t = threadIdx.x;
    for (int q = t; q < FIN * FOUT; q += 256) sW[q] = W[q];
    __syncthreads();

    int r = t >> 6;
    int d = t & 63;
    #pragma unroll
    for (int rr = 0; rr < 4; rr++) {
        int i = blockIdx.x * 16 + rr * 4 + r;
        const float4* h4 = (const float4*)(h + i * FIN);
        float acc = 0.f;
        #pragma unroll
        for (int kb = 0; kb < 32; kb++) {
            float4 hv = h4[kb];
            acc += hv.x * sW[(4 * kb + 0) * 64 + d];
            acc += hv.y * sW[(4 * kb + 1) * 64 + d];
            acc += hv.z * sW[(4 * kb + 2) * 64 + d];
            acc += hv.w * sW[(4 * kb + 3) * 64 + d];
        }
        g_Wh[i * 64 + d] = acc;
    }
}

// ---------------------------------------------------------------------------
// Kernel B: f1[i] = Wh[i]·a1, f2[i] = Wh[i]·a2.
// ---------------------------------------------------------------------------
__global__ void __launch_bounds__(256) k_f(const float* __restrict__ a) {
    int warp = blockIdx.x * 8 + (threadIdx.x >> 5);
    int lane = threadIdx.x & 31;
    float a1x = a[2 * lane], a1y = a[2 * lane + 1];
    float a2x = a[64 + 2 * lane], a2y = a[64 + 2 * lane + 1];
    for (int r = 0; r < 32; r++) {
        int i = warp * 32 + r;
        float2 v = ((const float2*)g_Wh)[i * 32 + lane];
        float p1 = v.x * a1x + v.y * a1y;
        float p2 = v.x * a2x + v.y * a2y;
        #pragma unroll
        for (int off = 16; off; off >>= 1) {
            p1 += __shfl_xor_sync(0xFFFFFFFFu, p1, off);
            p2 += __shfl_xor_sync(0xFFFFFFFFu, p2, off);
        }
        if (lane == 0) { g_f1[i] = p1; g_f2[i] = p2; }
    }
}

// ---------------------------------------------------------------------------
// Kernel C: g_maxf2 = max(f2).
// ---------------------------------------------------------------------------
__global__ void k_max() {
    __shared__ float s[256];
    float m = -INFINITY;
    for (int i = threadIdx.x; i < NN; i += 256) m = fmaxf(m, g_f2[i]);
    s[threadIdx.x] = m;
    __syncthreads();
    for (int st = 128; st; st >>= 1) {
        if (threadIdx.x < st) s[threadIdx.x] = fmaxf(s[threadIdx.x], s[threadIdx.x + st]);
        __syncthreads();
    }
    if (threadIdx.x == 0) g_maxf2 = s[0];
}

// ---------------------------------------------------------------------------
// Kernel C2: per-j factors (f2, exp(f2), exp(0.01*f2)). Only 16K exps total.
// ---------------------------------------------------------------------------
__global__ void __launch_bounds__(256) k_exp() {
    int j = blockIdx.x * 256 + threadIdx.x;
    float f2 = g_f2[j];
    g_JP[j] = make_float4(f2, __expf(f2), __expf(0.01f * f2), 0.f);
}

// ---------------------------------------------------------------------------
// Kernel D: streaming softmax-weighted aggregation + elu, NO per-pair exp:
//   s = f1_i + f2_j;  w = (s>0) ? E1_i*A_j : E2_i*B_j
// where E1_i=exp(f1_i-m_i), E2_i=exp(0.01*f1_i-m_i), m_i=lrelu(f1_i+maxf2).
// grid 128 (64 rows/block), block 256. thread t = dg*64+i owns 16 dims.
// Packed fma.rn.f32x2; prefetched Wh chunks; redundant per-thread sumw.
// ---------------------------------------------------------------------------
__global__ void __launch_bounds__(256) k_attn(float* __restrict__ out) {
    __shared__ float  sWh[64 * 64];   // 16 KB, [j][d]
    __shared__ float4 sJP[64];

    int t  = threadIdx.x;
    int i0 = blockIdx.x * 64;
    int i  = t & 63;
    int dg = t >> 6;

    float f1 = g_f1[i0 + i];
    float s0 = f1 + g_maxf2;
    float m  = fmaxf(s0, 0.01f * s0);          // exact row max of e_ij
    float E1 = __expf(f1 - m);
    float E2 = __expf(0.01f * f1 - m);

    unsigned long long acc[8];
    #pragma unroll
    for (int q = 0; q < 8; q++) acc[q] = 0ULL;
    float sumw = 0.f;

    // prefetch chunk 0
    float4 nxt[4];
    float4 np = make_float4(0.f, 0.f, 0.f, 0.f);
    {
        const float4* src = (const float4*)g_Wh;
        #pragma unroll
        for (int q = 0; q < 4; q++) nxt[q] = src[t + q * 256];
        if (t < 64) np = g_JP[t];
    }

    for (int jc = 0; jc < 128; jc++) {
        __syncthreads();                       // previous chunk fully consumed
        float4* dst = (float4*)sWh;
        #pragma unroll
        for (int q = 0; q < 4; q++) dst[t + q * 256] = nxt[q];
        if (t < 64) sJP[t] = np;
        __syncthreads();                       // chunk ready

        if (jc < 127) {                        // prefetch next chunk (L2 hit)
            const float4* src = (const float4*)(g_Wh + (jc + 1) * 4096);
            #pragma unroll
            for (int q = 0; q < 4; q++) nxt[q] = src[t + q * 256];
            if (t < 64) np = g_JP[(jc + 1) * 64 + t];
        }

        #pragma unroll 8
        for (int j = 0; j < 64; j++) {
            float4 pj = sJP[j];                // warp-uniform broadcast
            float s = f1 + pj.x;
            float w = (s > 0.f) ? E1 * pj.y : E2 * pj.z;
            sumw += w;
            unsigned int wu = __float_as_uint(w);
            unsigned long long w2;
            asm("mov.b64 %0, {%1, %2};" : "=l"(w2) : "r"(wu), "r"(wu));
            const ulonglong2* vp = (const ulonglong2*)(sWh + j * 64 + dg * 16);
            #pragma unroll
            for (int q = 0; q < 4; q++) {
                ulonglong2 v = vp[q];          // warp-uniform LDS.128 broadcast
                asm("fma.rn.f32x2 %0, %1, %2, %0;" : "+l"(acc[2 * q])     : "l"(v.x), "l"(w2));
                asm("fma.rn.f32x2 %0, %1, %2, %0;" : "+l"(acc[2 * q + 1]) : "l"(v.y), "l"(w2));
            }
        }
    }

    float inv = 1.0f / sumw;                   // identical across dg groups
    float res[16];
    #pragma unroll
    for (int q = 0; q < 8; q++) {
        float2 f;
        memcpy(&f, &acc[q], 8);
        res[2 * q]     = f.x * inv;
        res[2 * q + 1] = f.y * inv;
    }
    #pragma unroll
    for (int c = 0; c < 16; c++) {
        float x = res[c];
        res[c] = x > 0.f ? x : expm1f(x);      // elu
    }
    float4* o4 = (float4*)(out + (i0 + i) * 64 + dg * 16);
    #pragma unroll
    for (int q = 0; q < 4; q++)
        o4[q] = make_float4(res[4 * q], res[4 * q + 1], res[4 * q + 2], res[4 * q + 3]);
}

// ---------------------------------------------------------------------------
extern "C" void kernel_launch(void* const* d_in, const int* in_sizes, int n_in,
                              void* d_out, int out_size) {
    const float* h = (const float*)d_in[0];
    const float* W = (const float*)d_in[1];
    const float* a = (const float*)d_in[2];
    float* out = (float*)d_out;

    k_wh  <<<512, 256>>>(h, W);
    k_f   <<<32, 256>>>(a);
    k_max <<<1, 256>>>();
    k_exp <<<32, 256>>>();
    k_attn<<<128, 256>>>(out);
}

// round 3
// speedup vs baseline: 3.1209x; 2.8662x over previous
#include <cuda_runtime.h>
#include <math.h>

#define NN   8192
#define FIN  128
#define FOUT 64

// ---- scratch (device globals; no allocation allowed) ----------------------
__device__ float    g_Wh[NN * FOUT];       // 2 MB
__device__ float    g_f1[NN], g_f2[NN];
__device__ unsigned g_key[NN];             // sorted packed keys: f2-sortable(19b) | idx(13b)
__device__ float4   g_ABs[NN];             // sorted r: (A=e^f2, B=e^{0.01 f2}, f2, 0)
__device__ float    g_PA[NN * 64];         // chunk-local inclusive prefix of A*Wh
__device__ float    g_PB[NN * 64];         // chunk-local inclusive prefix of B*Wh
__device__ float    g_CTA[128 * 64], g_CTB[128 * 64];   // chunk totals
__device__ float    g_COA[128 * 64], g_COB[128 * 64];   // chunk exclusive offsets
__device__ float    g_TA[64];                            // grand totals of A*Wh
__device__ float    g_PSAl[NN], g_PSBl[NN];              // chunk-local scalar prefixes
__device__ float    g_CSA[128], g_CSB[128];              // scalar chunk totals
__device__ float    g_COSA[128], g_COSB[128];            // scalar chunk offsets
__device__ float    g_totSA;
__device__ int      g_kk[NN];
__device__ float2   g_c[NN];               // (E1/denom, E2/denom)

// ---------------------------------------------------------------------------
// A: Wh = h @ W   (8192x128 @ 128x64)
// ---------------------------------------------------------------------------
__global__ void __launch_bounds__(256) k_wh(const float* __restrict__ h,
                                            const float* __restrict__ W) {
    __shared__ float sW[FIN * FOUT];
    int t = threadIdx.x;
    for (int q = t; q < FIN * FOUT; q += 256) sW[q] = W[q];
    __syncthreads();
    int r = t >> 6, d = t & 63;
    #pragma unroll
    for (int rr = 0; rr < 4; rr++) {
        int i = blockIdx.x * 16 + rr * 4 + r;
        const float4* h4 = (const float4*)(h + i * FIN);
        float acc = 0.f;
        #pragma unroll
        for (int kb = 0; kb < 32; kb++) {
            float4 hv = h4[kb];
            acc += hv.x * sW[(4 * kb + 0) * 64 + d];
            acc += hv.y * sW[(4 * kb + 1) * 64 + d];
            acc += hv.z * sW[(4 * kb + 2) * 64 + d];
            acc += hv.w * sW[(4 * kb + 3) * 64 + d];
        }
        g_Wh[i * 64 + d] = acc;
    }
}

// ---------------------------------------------------------------------------
// B: f1 = Wh@a1, f2 = Wh@a2 (warp per 32 rows)
// ---------------------------------------------------------------------------
__global__ void __launch_bounds__(256) k_f(const float* __restrict__ a) {
    int warp = blockIdx.x * 8 + (threadIdx.x >> 5);
    int lane = threadIdx.x & 31;
    float a1x = a[2 * lane], a1y = a[2 * lane + 1];
    float a2x = a[64 + 2 * lane], a2y = a[64 + 2 * lane + 1];
    for (int r = 0; r < 32; r++) {
        int i = warp * 32 + r;
        float2 v = ((const float2*)g_Wh)[i * 32 + lane];
        float p1 = v.x * a1x + v.y * a1y;
        float p2 = v.x * a2x + v.y * a2y;
        #pragma unroll
        for (int off = 16; off; off >>= 1) {
            p1 += __shfl_xor_sync(0xFFFFFFFFu, p1, off);
            p2 += __shfl_xor_sync(0xFFFFFFFFu, p2, off);
        }
        if (lane == 0) { g_f1[i] = p1; g_f2[i] = p2; }
    }
}

// ---------------------------------------------------------------------------
// C: single-block bitonic sort of packed keys (19-bit f2-order | 13-bit idx),
//    then emit sorted (A,B,f2) table.
// ---------------------------------------------------------------------------
__device__ __forceinline__ unsigned f2key(float f) {
    unsigned u = __float_as_uint(f);
    return (u & 0x80000000u) ? ~u : (u | 0x80000000u);   // monotone in f
}

__global__ void __launch_bounds__(1024) k_sort() {
    __shared__ unsigned s[NN];   // 32 KB
    int t = threadIdx.x;
    for (int q = t; q < NN; q += 1024)
        s[q] = (f2key(g_f2[q]) & 0xFFFFE000u) | (unsigned)q;
    __syncthreads();
    for (int k = 2; k <= NN; k <<= 1) {
        for (int st = k >> 1; st > 0; st >>= 1) {
            for (int i = t; i < NN; i += 1024) {
                int p = i ^ st;
                if (p > i) {
                    unsigned a = s[i], b = s[p];
                    bool up = ((i & k) == 0);
                    if ((a > b) == up) { s[i] = b; s[p] = a; }
                }
            }
            __syncthreads();
        }
    }
    for (int q = t; q < NN; q += 1024) {
        unsigned key = s[q];
        g_key[q] = key;
        int j = key & 8191;
        float f2 = g_f2[j];
        g_ABs[q] = make_float4(__expf(f2), __expf(0.01f * f2), f2, 0.f);
    }
}

// ---------------------------------------------------------------------------
// D: chunk-local prefix scans. 128 chunks x 64 rows; block=64 threads (d).
// ---------------------------------------------------------------------------
__global__ void __launch_bounds__(64) k_scanV() {
    __shared__ int    sj[64];
    __shared__ float2 sab[64];
    int t = threadIdx.x, b = blockIdx.x, r0 = b * 64;
    sj[t] = g_key[r0 + t] & 8191;
    float4 ab4 = g_ABs[r0 + t];
    sab[t] = make_float2(ab4.x, ab4.y);
    __syncthreads();

    float accA = 0.f, accB = 0.f, accSA = 0.f, accSB = 0.f;
    #pragma unroll 16
    for (int r = 0; r < 64; r++) {
        int j = sj[r];
        float2 ab = sab[r];
        float wh = g_Wh[j * 64 + t];
        accA += ab.x * wh;
        accB += ab.y * wh;
        accSA += ab.x;
        accSB += ab.y;
        g_PA[(r0 + r) * 64 + t] = accA;
        g_PB[(r0 + r) * 64 + t] = accB;
        if (t == 0) { g_PSAl[r0 + r] = accSA; g_PSBl[r0 + r] = accSB; }
    }
    g_CTA[b * 64 + t] = accA;
    g_CTB[b * 64 + t] = accB;
    if (t == 0) { g_CSA[b] = accSA; g_CSB[b] = accSB; }
}

// ---------------------------------------------------------------------------
// E: scan the 128 chunk totals -> exclusive offsets + grand totals.
// ---------------------------------------------------------------------------
__global__ void __launch_bounds__(128) k_scanC() {
    int t = threadIdx.x;
    if (t < 64) {
        float offA = 0.f, offB = 0.f;
        #pragma unroll 8
        for (int b = 0; b < 128; b++) {
            g_COA[b * 64 + t] = offA;
            g_COB[b * 64 + t] = offB;
            offA += g_CTA[b * 64 + t];
            offB += g_CTB[b * 64 + t];
        }
        g_TA[t] = offA;
    } else if (t == 64) {
        float o = 0.f;
        #pragma unroll 8
        for (int b = 0; b < 128; b++) { g_COSA[b] = o; o += g_CSA[b]; }
        g_totSA = o;
    } else if (t == 65) {
        float o = 0.f;
        #pragma unroll 8
        for (int b = 0; b < 128; b++) { g_COSB[b] = o; o += g_CSB[b]; }
    }
}

// ---------------------------------------------------------------------------
// F: per-row threshold k_i (binary search) + normalization coefficients.
// ---------------------------------------------------------------------------
__global__ void __launch_bounds__(256) k_thresh() {
    int i = blockIdx.x * 256 + threadIdx.x;
    float f1 = g_f1[i];
    float maxf2 = g_ABs[NN - 1].z;
    float s0 = f1 + maxf2;
    float m = fmaxf(s0, 0.01f * s0);
    float E1 = __expf(f1 - m);
    float E2 = __expf(0.01f * f1 - m);

    unsigned T = (f2key(-f1) & 0xFFFFE000u) | 0x1FFFu;   // count keys <= T
    int lo = 0, hi = NN;
    while (lo < hi) {
        int mid = (lo + hi) >> 1;
        if (g_key[mid] <= T) lo = mid + 1; else hi = mid;
    }
    int k = lo;

    float psa = 0.f, psb = 0.f;
    if (k > 0) {
        int r = k - 1;
        psa = g_PSAl[r] + g_COSA[r >> 6];
        psb = g_PSBl[r] + g_COSB[r >> 6];
    }
    float denom = E1 * (g_totSA - psa) + E2 * psb;
    float inv = 1.0f / denom;
    g_kk[i] = k;
    g_c[i] = make_float2(E1 * inv, E2 * inv);
}

// ---------------------------------------------------------------------------
// G: gather output: out[i][d] = elu( c1*(TA[d]-PA(k,d)) + c2*PB(k,d) )
// ---------------------------------------------------------------------------
__global__ void __launch_bounds__(256) k_out(float* __restrict__ out) {
    int t = threadIdx.x;
    int i = blockIdx.x * 4 + (t >> 6);
    int d = t & 63;
    int k = g_kk[i];
    float2 c = g_c[i];
    float pa = 0.f, pb = 0.f;
    if (k > 0) {
        int r = k - 1;
        pa = g_PA[r * 64 + d] + g_COA[(r >> 6) * 64 + d];
        pb = g_PB[r * 64 + d] + g_COB[(r >> 6) * 64 + d];
    }
    float x = c.x * (g_TA[d] - pa) + c.y * pb;
    out[i * 64 + d] = x > 0.f ? x : expm1f(x);
}

// ---------------------------------------------------------------------------
extern "C" void kernel_launch(void* const* d_in, const int* in_sizes, int n_in,
                              void* d_out, int out_size) {
    const float* h = (const float*)d_in[0];
    const float* W = (const float*)d_in[1];
    const float* a = (const float*)d_in[2];
    float* out = (float*)d_out;

    k_wh    <<<512, 256>>>(h, W);
    k_f     <<<32, 256>>>(a);
    k_sort  <<<1, 1024>>>();
    k_scanV <<<128, 64>>>();
    k_scanC <<<1, 128>>>();
    k_thresh<<<32, 256>>>();
    k_out   <<<2048, 256>>>(out);
}

// round 4
// speedup vs baseline: 5.1918x; 1.6636x over previous
#include <cuda_runtime.h>
#include <math.h>

#define NN   8192
#define FIN  128
#define FOUT 64

// ---- scratch (device globals; no allocation allowed) ----------------------
__device__ float    g_Wh[NN * FOUT];       // 2 MB
__device__ float    g_f1[NN], g_f2[NN];
__device__ unsigned g_keyR[NN];            // 8 locally-sorted runs of 1024
__device__ unsigned g_key[NN];             // globally sorted keys
__device__ float4   g_ABs[NN];             // sorted r: (A=e^f2, B=e^{0.01 f2}, f2, 0)
__device__ float    g_PA[NN * 64];         // chunk-local inclusive prefix of A*Wh
__device__ float    g_PB[NN * 64];
__device__ float    g_CTA[128 * 64], g_CTB[128 * 64];   // chunk totals
__device__ float    g_COA[128 * 64], g_COB[128 * 64];   // chunk exclusive offsets
__device__ float    g_TA[64];
__device__ float    g_PSAl[NN], g_PSBl[NN];             // chunk-local scalar prefixes
__device__ float    g_CSA[128], g_CSB[128];
__device__ float    g_COSA[128], g_COSB[128];
__device__ float    g_totSA;
__device__ int      g_kk[NN];
__device__ float2   g_c[NN];

__device__ __forceinline__ unsigned f2key(float f) {
    unsigned u = __float_as_uint(f);
    return (u & 0x80000000u) ? ~u : (u | 0x80000000u);   // monotone in f
}

// ---------------------------------------------------------------------------
// A: Wh = h @ W, with fused f1/f2 epilogue (f1=Wh@a1, f2=Wh@a2).
// grid 512, block 256; 16 rows/block.
// ---------------------------------------------------------------------------
__global__ void __launch_bounds__(256) k_wh(const float* __restrict__ h,
                                            const float* __restrict__ W,
                                            const float* __restrict__ a) {
    __shared__ float sW[FIN * FOUT];
    __shared__ float sp1[8], sp2[8];
    int t = threadIdx.x;
    for (int q = t; q < FIN * FOUT; q += 256) sW[q] = W[q];
    int d = t & 63, r = t >> 6;
    float a1 = __ldg(a + d), a2 = __ldg(a + 64 + d);
    __syncthreads();

    #pragma unroll
    for (int rr = 0; rr < 4; rr++) {
        int i = blockIdx.x * 16 + rr * 4 + r;
        const float4* h4 = (const float4*)(h + i * FIN);
        float acc = 0.f;
        #pragma unroll
        for (int kb = 0; kb < 32; kb++) {
            float4 hv = h4[kb];
            acc += hv.x * sW[(4 * kb + 0) * 64 + d];
            acc += hv.y * sW[(4 * kb + 1) * 64 + d];
            acc += hv.z * sW[(4 * kb + 2) * 64 + d];
            acc += hv.w * sW[(4 * kb + 3) * 64 + d];
        }
        g_Wh[i * 64 + d] = acc;

        // fused f1/f2: row i spans warps 2r and 2r+1 (d 0..31 / 32..63)
        float p1 = acc * a1, p2 = acc * a2;
        #pragma unroll
        for (int off = 16; off; off >>= 1) {
            p1 += __shfl_xor_sync(0xFFFFFFFFu, p1, off);
            p2 += __shfl_xor_sync(0xFFFFFFFFu, p2, off);
        }
        int w = t >> 5;
        if ((t & 31) == 0) { sp1[w] = p1; sp2[w] = p2; }
        __syncthreads();
        if (t < 4) {
            g_f1[blockIdx.x * 16 + rr * 4 + t] = sp1[2 * t] + sp1[2 * t + 1];
            g_f2[blockIdx.x * 16 + rr * 4 + t] = sp2[2 * t] + sp2[2 * t + 1];
        }
        __syncthreads();
    }
}

// ---------------------------------------------------------------------------
// B: 8 blocks, each bitonic-sorts 1024 packed keys in smem -> g_keyR runs.
// ---------------------------------------------------------------------------
__global__ void __launch_bounds__(1024) k_sort8() {
    __shared__ unsigned s[1024];
    int t = threadIdx.x;
    int base = blockIdx.x * 1024;
    s[t] = (f2key(g_f2[base + t]) & 0xFFFFE000u) | (unsigned)(base + t);
    __syncthreads();
    for (int k = 2; k <= 1024; k <<= 1) {
        for (int st = k >> 1; st > 0; st >>= 1) {
            int p = t ^ st;
            if (p > t) {
                unsigned x = s[t], y = s[p];
                bool up = ((t & k) == 0);
                if ((x > y) == up) { s[t] = y; s[p] = x; }
            }
            __syncthreads();
        }
    }
    g_keyR[base + t] = s[t];
}

// ---------------------------------------------------------------------------
// C: rank-merge the 8 runs. Each element: global rank = local pos + sum of
//    lower_bound counts in the other 7 runs (keys unique -> permutation).
//    Scatter key + (A,B,f2) to sorted position.
// ---------------------------------------------------------------------------
__global__ void __launch_bounds__(256) k_rank() {
    int i = blockIdx.x * 256 + threadIdx.x;
    unsigned key = g_keyR[i];
    int rank = i & 1023;
    int myrun = i >> 10;
    #pragma unroll
    for (int b = 0; b < 8; b++) {
        if (b == myrun) continue;
        const unsigned* run = g_keyR + b * 1024;
        int lo = 0, hi = 1024;
        while (lo < hi) {
            int mid = (lo + hi) >> 1;
            if (run[mid] < key) lo = mid + 1; else hi = mid;
        }
        rank += lo;
    }
    g_key[rank] = key;
    int j = key & 8191;
    float f2 = g_f2[j];
    g_ABs[rank] = make_float4(__expf(f2), __expf(0.01f * f2), f2, 0.f);
}

// ---------------------------------------------------------------------------
// D: chunk-local prefix scans, 256-thread version.
// Thread t: d = t&63, segment rg = t>>6 owns rows rg*16..rg*16+15 (contig).
// 16 independent gathers (MLP=16) -> register prefix -> segment-offset fixup.
// ---------------------------------------------------------------------------
__global__ void __launch_bounds__(256) k_scanV() {
    __shared__ int    sj[64];
    __shared__ float2 sab[64];
    __shared__ float  segA[4][64], segB[4][64];
    __shared__ float  segSA[4], segSB[4];
    __shared__ float  sPSa[64], sPSb[64];

    int t = threadIdx.x, b = blockIdx.x, r0 = b * 64;
    int d = t & 63, rg = t >> 6;

    if (t < 64) {
        sj[t] = g_key[r0 + t] & 8191;
        float4 q4 = g_ABs[r0 + t];
        sab[t] = make_float2(q4.x, q4.y);
    }
    __syncthreads();

    // vector: register prefix over 16 contiguous rows
    float vA[16], vB[16];
    float accA = 0.f, accB = 0.f;
    #pragma unroll
    for (int q = 0; q < 16; q++) {
        int r = rg * 16 + q;
        float2 ab = sab[r];
        float wh = g_Wh[sj[r] * 64 + d];     // independent gathers, MLP=16
        accA += ab.x * wh;
        accB += ab.y * wh;
        vA[q] = accA; vB[q] = accB;
    }
    segA[rg][d] = accA;
    segB[rg][d] = accB;

    // scalar: threads 0..3 handle segment rg2=t
    if (t < 4) {
        float sa = 0.f, sb = 0.f;
        #pragma unroll
        for (int q = 0; q < 16; q++) {
            float2 ab = sab[t * 16 + q];
            sa += ab.x; sb += ab.y;
            sPSa[t * 16 + q] = sa;
            sPSb[t * 16 + q] = sb;
        }
        segSA[t] = sa; segSB[t] = sb;
    }
    __syncthreads();

    float offA = 0.f, offB = 0.f;
    #pragma unroll
    for (int g = 0; g < 3; g++)
        if (g < rg) { offA += segA[g][d]; offB += segB[g][d]; }

    #pragma unroll
    for (int q = 0; q < 16; q++) {
        int r = r0 + rg * 16 + q;
        g_PA[r * 64 + d] = vA[q] + offA;
        g_PB[r * 64 + d] = vB[q] + offB;
    }
    if (rg == 3) {
        g_CTA[b * 64 + d] = offA + accA;
        g_CTB[b * 64 + d] = offB + accB;
    }

    if (t < 4) {
        float oa = 0.f, ob = 0.f;
        for (int g = 0; g < t; g++) { oa += segSA[g]; ob += segSB[g]; }
        #pragma unroll
        for (int q = 0; q < 16; q++) {
            int r = r0 + t * 16 + q;
            g_PSAl[r] = sPSa[t * 16 + q] + oa;
            g_PSBl[r] = sPSb[t * 16 + q] + ob;
        }
        if (t == 3) {
            g_CSA[b] = oa + segSA[3];
            g_CSB[b] = ob + segSB[3];
        }
    }
}

// ---------------------------------------------------------------------------
// E: scan the 128 chunk totals -> exclusive offsets + grand totals.
// ---------------------------------------------------------------------------
__global__ void __launch_bounds__(128) k_scanC() {
    int t = threadIdx.x;
    if (t < 64) {
        float offA = 0.f, offB = 0.f;
        #pragma unroll 8
        for (int b = 0; b < 128; b++) {
            g_COA[b * 64 + t] = offA;
            g_COB[b * 64 + t] = offB;
            offA += g_CTA[b * 64 + t];
            offB += g_CTB[b * 64 + t];
        }
        g_TA[t] = offA;
    } else if (t == 64) {
        float o = 0.f;
        #pragma unroll 8
        for (int b = 0; b < 128; b++) { g_COSA[b] = o; o += g_CSA[b]; }
        g_totSA = o;
    } else if (t == 65) {
        float o = 0.f;
        #pragma unroll 8
        for (int b = 0; b < 128; b++) { g_COSB[b] = o; o += g_CSB[b]; }
    }
}

// ---------------------------------------------------------------------------
// F: per-row threshold k_i (binary search) + normalization coefficients.
// ---------------------------------------------------------------------------
__global__ void __launch_bounds__(256) k_thresh() {
    int i = blockIdx.x * 256 + threadIdx.x;
    float f1 = g_f1[i];
    float maxf2 = g_ABs[NN - 1].z;
    float s0 = f1 + maxf2;
    float m = fmaxf(s0, 0.01f * s0);
    float E1 = __expf(f1 - m);
    float E2 = __expf(0.01f * f1 - m);

    unsigned T = (f2key(-f1) & 0xFFFFE000u) | 0x1FFFu;
    int lo = 0, hi = NN;
    while (lo < hi) {
        int mid = (lo + hi) >> 1;
        if (g_key[mid] <= T) lo = mid + 1; else hi = mid;
    }
    int k = lo;

    float psa = 0.f, psb = 0.f;
    if (k > 0) {
        int r = k - 1;
        psa = g_PSAl[r] + g_COSA[r >> 6];
        psb = g_PSBl[r] + g_COSB[r >> 6];
    }
    float denom = E1 * (g_totSA - psa) + E2 * psb;
    float inv = 1.0f / denom;
    g_kk[i] = k;
    g_c[i] = make_float2(E1 * inv, E2 * inv);
}

// ---------------------------------------------------------------------------
// G: out[i][d] = elu( c1*(TA[d]-PA(k,d)) + c2*PB(k,d) )
// ---------------------------------------------------------------------------
__global__ void __launch_bounds__(256) k_out(float* __restrict__ out) {
    int t = threadIdx.x;
    int i = blockIdx.x * 4 + (t >> 6);
    int d = t & 63;
    int k = g_kk[i];
    float2 c = g_c[i];
    float pa = 0.f, pb = 0.f;
    if (k > 0) {
        int r = k - 1;
        pa = g_PA[r * 64 + d] + g_COA[(r >> 6) * 64 + d];
        pb = g_PB[r * 64 + d] + g_COB[(r >> 6) * 64 + d];
    }
    float x = c.x * (g_TA[d] - pa) + c.y * pb;
    out[i * 64 + d] = x > 0.f ? x : expm1f(x);
}

// ---------------------------------------------------------------------------
extern "C" void kernel_launch(void* const* d_in, const int* in_sizes, int n_in,
                              void* d_out, int out_size) {
    const float* h = (const float*)d_in[0];
    const float* W = (const float*)d_in[1];
    const float* a = (const float*)d_in[2];
    float* out = (float*)d_out;

    k_wh    <<<512, 256>>>(h, W, a);
    k_sort8 <<<8, 1024>>>();
    k_rank  <<<32, 256>>>();
    k_scanV <<<128, 256>>>();
    k_scanC <<<1, 128>>>();
    k_thresh<<<32, 256>>>();
    k_out   <<<2048, 256>>>(out);
}

// round 6
// speedup vs baseline: 6.6840x; 1.2874x over previous
#include <cuda_runtime.h>
#include <math.h>

#define NN   8192
#define NBLK 128

// ---- scratch (device globals) ---------------------------------------------
__device__ float    g_Wh[NN * 64];
__device__ float    g_f1[NN], g_f2[NN];
__device__ unsigned g_keyR[NN];            // 8 locally-sorted runs of 1024
__device__ unsigned g_key[NN];             // globally sorted keys
__device__ float4   g_ABs[NN];             // sorted: (A=e^f2, B=e^{.01 f2}, f2, 0)
__device__ float    g_PA[NN * 64], g_PB[NN * 64];   // chunk-local prefixes
__device__ float    g_CTA[128 * 64], g_CTB[128 * 64];
__device__ float    g_COA[128 * 64], g_COB[128 * 64];
__device__ float    g_TA[64];
__device__ float    g_PSAl[NN], g_PSBl[NN];
__device__ float    g_CSA[128], g_CSB[128];
__device__ float    g_COSA[128], g_COSB[128];
__device__ float    g_totSA;
__device__ unsigned g_barGen, g_barCnt;    // zero-init

__device__ __forceinline__ unsigned f2key(float f) {
    unsigned u = __float_as_uint(f);
    return (u & 0x80000000u) ? ~u : (u | 0x80000000u);
}

// grid barrier: all NBLK CTAs resident (NBLK < #SMs) -> deadlock-free.
__device__ __forceinline__ void gsync() {
    __syncthreads();
    if (threadIdx.x == 0) {
        unsigned gen = atomicAdd(&g_barGen, 0u);
        __threadfence();
        if (atomicAdd(&g_barCnt, 1u) == NBLK - 1) {
            atomicExch(&g_barCnt, 0u);
            __threadfence();
            atomicExch(&g_barGen, gen + 1u);
        } else {
            while (atomicAdd(&g_barGen, 0u) == gen) { }
        }
        __threadfence();
    }
    __syncthreads();
}

__global__ void __launch_bounds__(256) k_all(const float* __restrict__ h,
                                             const float* __restrict__ W,
                                             const float* __restrict__ a,
                                             float* __restrict__ out) {
    __shared__ float    sW[128 * 64];      // 32 KB (phase 1)
    __shared__ unsigned sk[1024];          // 4 KB  (sort)
    __shared__ int      sj[64];
    __shared__ float2   sab[64];
    __shared__ float    segA[4][64], segB[4][64];
    __shared__ float    segSA[4], segSB[4];
    __shared__ float    sPSa[64], sPSb[64];
    __shared__ float    sOA[4][64], sOB[4][64];

    const int t = threadIdx.x, b = blockIdx.x;

    // ============ P1: Wh = h@W  (+ fused f1/f2) =============================
    {
        for (int q = t; q < 4096; q += 256)
            ((float2*)sW)[q] = ((const float2*)W)[q];
        __syncthreads();

        int d2 = t & 31, rs = t >> 5;
        int row0 = b * 64 + rs * 8;
        float2 a1v = *(const float2*)(a + 2 * d2);
        float2 a2v = *(const float2*)(a + 64 + 2 * d2);

        float2 acc[8];
        #pragma unroll
        for (int r = 0; r < 8; r++) acc[r] = make_float2(0.f, 0.f);

        #pragma unroll 4
        for (int kb = 0; kb < 32; kb++) {
            float2 w0 = *(const float2*)(sW + (4 * kb + 0) * 64 + 2 * d2);
            float2 w1 = *(const float2*)(sW + (4 * kb + 1) * 64 + 2 * d2);
            float2 w2 = *(const float2*)(sW + (4 * kb + 2) * 64 + 2 * d2);
            float2 w3 = *(const float2*)(sW + (4 * kb + 3) * 64 + 2 * d2);
            #pragma unroll
            for (int r = 0; r < 8; r++) {
                float4 hv = *(const float4*)(h + (row0 + r) * 128 + 4 * kb); // warp-broadcast
                acc[r].x += hv.x * w0.x + hv.y * w1.x + hv.z * w2.x + hv.w * w3.x;
                acc[r].y += hv.x * w0.y + hv.y * w1.y + hv.z * w2.y + hv.w * w3.y;
            }
        }
        #pragma unroll
        for (int r = 0; r < 8; r++)
            *(float2*)(g_Wh + (row0 + r) * 64 + 2 * d2) = acc[r];

        #pragma unroll
        for (int r = 0; r < 8; r++) {
            float p1 = acc[r].x * a1v.x + acc[r].y * a1v.y;
            float p2 = acc[r].x * a2v.x + acc[r].y * a2v.y;
            #pragma unroll
            for (int off = 16; off; off >>= 1) {
                p1 += __shfl_xor_sync(0xFFFFFFFFu, p1, off);
                p2 += __shfl_xor_sync(0xFFFFFFFFu, p2, off);
            }
            if (d2 == 0) { g_f1[row0 + r] = p1; g_f2[row0 + r] = p2; }
        }
    }
    gsync();

    // ============ P2: 8 blocks bitonic-sort 1024 keys each ==================
    if (b < 8) {
        int base = b * 1024;
        for (int q = t; q < 1024; q += 256)
            sk[q] = (f2key(g_f2[base + q]) & 0xFFFFE000u) | (unsigned)(base + q);
        __syncthreads();
        for (int k = 2; k <= 1024; k <<= 1) {
            for (int j = k >> 1; j; j >>= 1) {
                for (int i = t; i < 1024; i += 256) {
                    int p = i ^ j;
                    if (p > i) {
                        unsigned x = sk[i], y = sk[p];
                        bool up = ((i & k) == 0);
                        if ((x > y) == up) { sk[i] = y; sk[p] = x; }
                    }
                }
                __syncthreads();
            }
        }
        for (int q = t; q < 1024; q += 256) g_keyR[base + q] = sk[q];
    }
    gsync();

    // ============ P3: rank-merge (keys unique -> exact permutation) =========
    if (b < 32) {
        int i = b * 256 + t;
        unsigned key = g_keyR[i];
        int rank = i & 1023;
        int myrun = i >> 10;
        #pragma unroll
        for (int rb = 0; rb < 8; rb++) {
            if (rb == myrun) continue;
            const unsigned* run = g_keyR + rb * 1024;
            int lo = 0, hi = 1024;
            while (lo < hi) {
                int mid = (lo + hi) >> 1;
                if (run[mid] < key) lo = mid + 1; else hi = mid;
            }
            rank += lo;
        }
        g_key[rank] = key;
        int j = key & 8191;
        float f2 = g_f2[j];
        g_ABs[rank] = make_float4(__expf(f2), __expf(0.01f * f2), f2, 0.f);
    }
    gsync();

    // ============ P4: chunk-local prefix scans (block b = chunk b) ==========
    {
        int d = t & 63, rg = t >> 6, r0 = b * 64;
        if (t < 64) {
            sj[t] = g_key[r0 + t] & 8191;
            float4 q4 = g_ABs[r0 + t];
            sab[t] = make_float2(q4.x, q4.y);
        }
        __syncthreads();

        float vA[16], vB[16];
        float accA = 0.f, accB = 0.f;
        #pragma unroll
        for (int q = 0; q < 16; q++) {
            int r = rg * 16 + q;
            float2 ab = sab[r];
            float wh = g_Wh[sj[r] * 64 + d];      // MLP=16 gathers
            accA += ab.x * wh;
            accB += ab.y * wh;
            vA[q] = accA; vB[q] = accB;
        }
        segA[rg][d] = accA;
        segB[rg][d] = accB;

        if (t < 4) {
            float sa = 0.f, sb = 0.f;
            #pragma unroll
            for (int q = 0; q < 16; q++) {
                float2 ab = sab[t * 16 + q];
                sa += ab.x; sb += ab.y;
                sPSa[t * 16 + q] = sa;
                sPSb[t * 16 + q] = sb;
            }
            segSA[t] = sa; segSB[t] = sb;
        }
        __syncthreads();

        float offA = 0.f, offB = 0.f;
        #pragma unroll
        for (int g = 0; g < 3; g++)
            if (g < rg) { offA += segA[g][d]; offB += segB[g][d]; }

        #pragma unroll
        for (int q = 0; q < 16; q++) {
            int r = r0 + rg * 16 + q;
            g_PA[r * 64 + d] = vA[q] + offA;
            g_PB[r * 64 + d] = vB[q] + offB;
        }
        if (rg == 3) {
            g_CTA[b * 64 + d] = offA + accA;
            g_CTB[b * 64 + d] = offB + accB;
        }
        if (t < 4) {
            float oa = 0.f, ob = 0.f;
            for (int g = 0; g < t; g++) { oa += segSA[g]; ob += segSB[g]; }
            #pragma unroll
            for (int q = 0; q < 16; q++) {
                int r = r0 + t * 16 + q;
                g_PSAl[r] = sPSa[t * 16 + q] + oa;
                g_PSBl[r] = sPSb[t * 16 + q] + ob;
            }
            if (t == 3) {
                g_CSA[b] = oa + segSA[3];
                g_CSB[b] = ob + segSB[3];
            }
        }
    }
    gsync();

    // ============ P5: chunk offsets (each block its own chunk, parallel) ====
    {
        int d = t & 63, g = t >> 6;
        float oa = 0.f, ob = 0.f;
        for (int c = g; c < b; c += 4) {
            oa += g_CTA[c * 64 + d];
            ob += g_CTB[c * 64 + d];
        }
        sOA[g][d] = oa; sOB[g][d] = ob;
        __syncthreads();
        if (g == 0) {
            float A = sOA[0][d] + sOA[1][d] + sOA[2][d] + sOA[3][d];
            float B = sOB[0][d] + sOB[1][d] + sOB[2][d] + sOB[3][d];
            g_COA[b * 64 + d] = A;
            g_COB[b * 64 + d] = B;
            if (b == 127) g_TA[d] = A + g_CTA[127 * 64 + d];
        }
        if (b == 0 && t < 128) {
            float o = 0.f;
            for (int c = 0; c < t; c++) o += g_CSA[c];
            g_COSA[t] = o;
            if (t == 127) g_totSA = o + g_CSA[127];
        }
        if (b == 1 && t < 128) {
            float o = 0.f;
            for (int c = 0; c < t; c++) o += g_CSB[c];
            g_COSB[t] = o;
        }
    }
    gsync();

    // ============ P6: threshold + output ====================================
    {
        int i  = b * 64 + (t >> 2);
        int dq = (t & 3) * 16;
        float f1 = g_f1[i];
        float maxf2 = g_ABs[NN - 1].z;
        float s0 = f1 + maxf2;
        float m  = fmaxf(s0, 0.01f * s0);
        float E1 = __expf(f1 - m);
        float E2 = __expf(0.01f * f1 - m);

        unsigned T = (f2key(-f1) & 0xFFFFE000u) | 0x1FFFu;
        int lo = 0, hi = NN;
        while (lo < hi) {
            int mid = (lo + hi) >> 1;
            if (g_key[mid] <= T) lo = mid + 1; else hi = mid;
        }
        int k = lo;

        float c1, c2;
        {
            float psa = 0.f, psb = 0.f;
            if (k > 0) {
                int r = k - 1;
                psa = g_PSAl[r] + g_COSA[r >> 6];
                psb = g_PSBl[r] + g_COSB[r >> 6];
            }
            float inv = 1.0f / (E1 * (g_totSA - psa) + E2 * psb);
            c1 = E1 * inv; c2 = E2 * inv;
        }

        #pragma unroll
        for (int q = 0; q < 4; q++) {
            float4 pa = make_float4(0.f, 0.f, 0.f, 0.f), pb = pa;
            if (k > 0) {
                int r = k - 1, cb = (r >> 6) * 64;
                float4 p = *(const float4*)(g_PA + r * 64 + dq + 4 * q);
                float4 o = *(const float4*)(g_COA + cb + dq + 4 * q);
                pa = make_float4(p.x + o.x, p.y + o.y, p.z + o.z, p.w + o.w);
                p = *(const float4*)(g_PB + r * 64 + dq + 4 * q);
                o = *(const float4*)(g_COB + cb + dq + 4 * q);
                pb = make_float4(p.x + o.x, p.y + o.y, p.z + o.z, p.w + o.w);
            }
            float4 ta = *(const float4*)(g_TA + dq + 4 * q);
            float4 res;
            res.x = c1 * (ta.x - pa.x) + c2 * pb.x;
            res.y = c1 * (ta.y - pa.y) + c2 * pb.y;
            res.z = c1 * (ta.z - pa.z) + c2 * pb.z;
            res.w = c1 * (ta.w - pa.w) + c2 * pb.w;
            res.x = res.x > 0.f ? res.x : expm1f(res.x);
            res.y = res.y > 0.f ? res.y : expm1f(res.y);
            res.z = res.z > 0.f ? res.z : expm1f(res.z);
            res.w = res.w > 0.f ? res.w : expm1f(res.w);
            *(float4*)(out + i * 64 + dq + 4 * q) = res;
        }
    }
}

// ---------------------------------------------------------------------------
extern "C" void kernel_launch(void* const* d_in, const int* in_sizes, int n_in,
                              void* d_out, int out_size) {
    const float* h = (const float*)d_in[0];
    const float* W = (const float*)d_in[1];
    const float* a = (const float*)d_in[2];
    float* out = (float*)d_out;

    k_all<<<NBLK, 256>>>(h, W, a, out);
}

// round 8
// speedup vs baseline: 9.2816x; 1.3886x over previous
#include <cuda_runtime.h>
#include <math.h>

#define NN   8192
#define NBLK 128

// ---- scratch (device globals) ---------------------------------------------
__device__ float    g_Wh[NN * 64];
__device__ float    g_f1[NN], g_f2[NN];
__device__ unsigned g_keyR[NN];            // 32 locally-sorted runs of 256
__device__ unsigned g_key[NN];             // globally sorted keys
__device__ float4   g_ABs[NN];             // sorted: (A=e^f2, B=e^{.01 f2}, f2, 0)
__device__ float    g_PA[NN * 64], g_PB[NN * 64];
__device__ float    g_CTA[128 * 64], g_CTB[128 * 64];
__device__ float    g_COA[128 * 64], g_COB[128 * 64];
__device__ float    g_TA[64];
__device__ float    g_PSAl[NN], g_PSBl[NN];
__device__ float    g_CSA[128], g_CSB[128];
__device__ float    g_COSA[128], g_COSB[128];
__device__ float    g_totSA;
__device__ volatile unsigned g_barGen;     // zero-init
__device__ unsigned g_barCnt;              // zero-init

__device__ __forceinline__ unsigned f2key(float f) {
    unsigned u = __float_as_uint(f);
    return (u & 0x80000000u) ? ~u : (u | 0x80000000u);
}

// Grid barrier: all NBLK CTAs resident. Arrive = 1 atomic; WAIT = plain
// volatile loads (no L2 atomic-ALU serialization); release = plain store.
__device__ __forceinline__ void gsync() {
    __syncthreads();
    if (threadIdx.x == 0) {
        __threadfence();
        unsigned gen = g_barGen;
        if (atomicAdd(&g_barCnt, 1u) == NBLK - 1) {
            g_barCnt = 0;
            __threadfence();
            g_barGen = gen + 1;
        } else {
            while (g_barGen == gen) { }
        }
        __threadfence();
    }
    __syncthreads();
}

__global__ void __launch_bounds__(256) k_all(const float* __restrict__ h,
                                             const float* __restrict__ W,
                                             const float* __restrict__ a,
                                             float* __restrict__ out) {
    // 32 KB region reused: P1 W-tile -> P2 sort buf -> P3..P6 staged run-keys
    __shared__ union {
        float    sW[128 * 64];     // P1
        unsigned sk[256];          // P2 (per-block sort)
        unsigned keys[8192];       // P3 staging, reused by P6
    } sm;
    __shared__ int    sj[64];
    __shared__ float2 sab[64];
    __shared__ float  segA[4][64], segB[4][64];
    __shared__ float  segSA[4], segSB[4];
    __shared__ float  sPSa[64], sPSb[64];
    __shared__ float  sOA[4][64], sOB[4][64];

    const int t = threadIdx.x, b = blockIdx.x;

    // ============ P1: Wh = h@W  (+ fused f1/f2) =============================
    {
        for (int q = t; q < 4096; q += 256)
            ((float2*)sm.sW)[q] = ((const float2*)W)[q];
        __syncthreads();

        int d2 = t & 31, rs = t >> 5;
        int row0 = b * 64 + rs * 8;
        float2 a1v = *(const float2*)(a + 2 * d2);
        float2 a2v = *(const float2*)(a + 64 + 2 * d2);

        float2 acc[8];
        #pragma unroll
        for (int r = 0; r < 8; r++) acc[r] = make_float2(0.f, 0.f);

        #pragma unroll 4
        for (int kb = 0; kb < 32; kb++) {
            float2 w0 = *(const float2*)(sm.sW + (4 * kb + 0) * 64 + 2 * d2);
            float2 w1 = *(const float2*)(sm.sW + (4 * kb + 1) * 64 + 2 * d2);
            float2 w2 = *(const float2*)(sm.sW + (4 * kb + 2) * 64 + 2 * d2);
            float2 w3 = *(const float2*)(sm.sW + (4 * kb + 3) * 64 + 2 * d2);
            #pragma unroll
            for (int r = 0; r < 8; r++) {
                float4 hv = *(const float4*)(h + (row0 + r) * 128 + 4 * kb);
                acc[r].x += hv.x * w0.x + hv.y * w1.x + hv.z * w2.x + hv.w * w3.x;
                acc[r].y += hv.x * w0.y + hv.y * w1.y + hv.z * w2.y + hv.w * w3.y;
            }
        }
        #pragma unroll
        for (int r = 0; r < 8; r++)
            *(float2*)(g_Wh + (row0 + r) * 64 + 2 * d2) = acc[r];

        #pragma unroll
        for (int r = 0; r < 8; r++) {
            float p1 = acc[r].x * a1v.x + acc[r].y * a1v.y;
            float p2 = acc[r].x * a2v.x + acc[r].y * a2v.y;
            #pragma unroll
            for (int off = 16; off; off >>= 1) {
                p1 += __shfl_xor_sync(0xFFFFFFFFu, p1, off);
                p2 += __shfl_xor_sync(0xFFFFFFFFu, p2, off);
            }
            if (d2 == 0) { g_f1[row0 + r] = p1; g_f2[row0 + r] = p2; }
        }
    }
    gsync();

    // ============ P2: 32 blocks bitonic-sort 256 keys each (1 elem/thread) ==
    if (b < 32) {
        int base = b * 256;
        sm.sk[t] = (f2key(g_f2[base + t]) & 0xFFFFE000u) | (unsigned)(base + t);
        __syncthreads();
        #pragma unroll 1
        for (int k = 2; k <= 256; k <<= 1) {
            for (int j = k >> 1; j; j >>= 1) {
                int p = t ^ j;
                unsigned x = sm.sk[t], y = sm.sk[p];
                unsigned mn = min(x, y), mx = max(x, y);
                bool up = ((t & k) == 0);
                unsigned keep = ((t < p) == up) ? mn : mx;
                __syncthreads();
                sm.sk[t] = keep;
                __syncthreads();
            }
        }
        g_keyR[base + t] = sm.sk[t];
    }
    gsync();

    // ============ P3: rank-merge with all runs staged in smem ===============
    // Every block: stage 8192 keys (32KB) -> LDS binary searches.
    // Element e = b*64 + t/4; sub-thread (t&3) searches 8 runs; shfl-combine.
    {
        for (int q = t; q < 2048; q += 256)
            ((uint4*)sm.keys)[q] = ((const uint4*)g_keyR)[q];
        __syncthreads();

        int e = b * 64 + (t >> 2), sub = t & 3;
        unsigned key = sm.keys[e];
        int own = e >> 8;
        int cnt = 0;
        #pragma unroll
        for (int r = sub * 8; r < sub * 8 + 8; r++) {
            if (r == own) continue;
            const unsigned* run = sm.keys + r * 256;
            int lo = 0, hi = 256;
            while (lo < hi) {
                int mid = (lo + hi) >> 1;
                if (run[mid] < key) lo = mid + 1; else hi = mid;
            }
            cnt += lo;
        }
        cnt += __shfl_xor_sync(0xFFFFFFFFu, cnt, 1);
        cnt += __shfl_xor_sync(0xFFFFFFFFu, cnt, 2);
        if (sub == 0) {
            int rank = (e & 255) + cnt;
            g_key[rank] = key;
            int j = key & 8191;
            float f2 = g_f2[j];
            g_ABs[rank] = make_float4(__expf(f2), __expf(0.01f * f2), f2, 0.f);
        }
    }
    gsync();

    // ============ P4: chunk-local prefix scans (block b = chunk b) ==========
    {
        int d = t & 63, rg = t >> 6, r0 = b * 64;
        if (t < 64) {
            sj[t] = g_key[r0 + t] & 8191;
            float4 q4 = g_ABs[r0 + t];
            sab[t] = make_float2(q4.x, q4.y);
        }
        __syncthreads();

        float vA[16], vB[16];
        float accA = 0.f, accB = 0.f;
        #pragma unroll
        for (int q = 0; q < 16; q++) {
            int r = rg * 16 + q;
            float2 ab = sab[r];
            float wh = g_Wh[sj[r] * 64 + d];      // MLP=16 gathers
            accA += ab.x * wh;
            accB += ab.y * wh;
            vA[q] = accA; vB[q] = accB;
        }
        segA[rg][d] = accA;
        segB[rg][d] = accB;

        if (t < 4) {
            float sa = 0.f, sb = 0.f;
            #pragma unroll
            for (int q = 0; q < 16; q++) {
                float2 ab = sab[t * 16 + q];
                sa += ab.x; sb += ab.y;
                sPSa[t * 16 + q] = sa;
                sPSb[t * 16 + q] = sb;
            }
            segSA[t] = sa; segSB[t] = sb;
        }
        __syncthreads();

        float offA = 0.f, offB = 0.f;
        #pragma unroll
        for (int g = 0; g < 3; g++)
            if (g < rg) { offA += segA[g][d]; offB += segB[g][d]; }

        #pragma unroll
        for (int q = 0; q < 16; q++) {
            int r = r0 + rg * 16 + q;
            g_PA[r * 64 + d] = vA[q] + offA;
            g_PB[r * 64 + d] = vB[q] + offB;
        }
        if (rg == 3) {
            g_CTA[b * 64 + d] = offA + accA;
            g_CTB[b * 64 + d] = offB + accB;
        }
        if (t < 4) {
            float oa = 0.f, ob = 0.f;
            for (int g = 0; g < t; g++) { oa += segSA[g]; ob += segSB[g]; }
            #pragma unroll
            for (int q = 0; q < 16; q++) {
                int r = r0 + t * 16 + q;
                g_PSAl[r] = sPSa[t * 16 + q] + oa;
                g_PSBl[r] = sPSb[t * 16 + q] + ob;
            }
            if (t == 3) {
                g_CSA[b] = oa + segSA[3];
                g_CSB[b] = ob + segSB[3];
            }
        }
    }
    gsync();

    // ============ P5: chunk offsets (parallel, each block its own chunk) ====
    {
        int d = t & 63, g = t >> 6;
        float oa = 0.f, ob = 0.f;
        for (int c = g; c < b; c += 4) {
            oa += g_CTA[c * 64 + d];
            ob += g_CTB[c * 64 + d];
        }
        sOA[g][d] = oa; sOB[g][d] = ob;
        __syncthreads();
        if (g == 0) {
            float A = sOA[0][d] + sOA[1][d] + sOA[2][d] + sOA[3][d];
            float B = sOB[0][d] + sOB[1][d] + sOB[2][d] + sOB[3][d];
            g_COA[b * 64 + d] = A;
            g_COB[b * 64 + d] = B;
            if (b == 127) g_TA[d] = A + g_CTA[127 * 64 + d];
        }
        if (b == 0 && t < 128) {
            float o = 0.f;
            for (int c = 0; c < t; c++) o += g_CSA[c];
            g_COSA[t] = o;
            if (t == 127) g_totSA = o + g_CSA[127];
        }
        if (b == 1 && t < 128) {
            float o = 0.f;
            for (int c = 0; c < t; c++) o += g_CSB[c];
            g_COSB[t] = o;
        }
    }
    gsync();

    // ============ P6: threshold (LDS search on staged runs) + output ========
    {
        int e = t >> 2, sub = t & 3;
        int i = b * 64 + e;
        float f1 = g_f1[i];
        float maxf2 = g_ABs[NN - 1].z;
        float s0 = f1 + maxf2;
        float m  = fmaxf(s0, 0.01f * s0);
        float E1 = __expf(f1 - m);
        float E2 = __expf(0.01f * f1 - m);

        // count of sorted keys <= T  ==  sum of per-run counts (runs still in smem)
        unsigned T = (f2key(-f1) & 0xFFFFE000u) | 0x1FFFu;
        int cnt = 0;
        #pragma unroll
        for (int r = sub * 8; r < sub * 8 + 8; r++) {
            const unsigned* run = sm.keys + r * 256;
            int lo = 0, hi = 256;
            while (lo < hi) {
                int mid = (lo + hi) >> 1;
                if (run[mid] <= T) lo = mid + 1; else hi = mid;
            }
            cnt += lo;
        }
        cnt += __shfl_xor_sync(0xFFFFFFFFu, cnt, 1);
        cnt += __shfl_xor_sync(0xFFFFFFFFu, cnt, 2);
        int k = cnt;

        float c1, c2;
        {
            float psa = 0.f, psb = 0.f;
            if (k > 0) {
                int r = k - 1;
                psa = g_PSAl[r] + g_COSA[r >> 6];
                psb = g_PSBl[r] + g_COSB[r >> 6];
            }
            float inv = 1.0f / (E1 * (g_totSA - psa) + E2 * psb);
            c1 = E1 * inv; c2 = E2 * inv;
        }

        int dq = sub * 16;
        #pragma unroll
        for (int q = 0; q < 4; q++) {
            float4 pa = make_float4(0.f, 0.f, 0.f, 0.f), pb = pa;
            if (k > 0) {
                int r = k - 1, cb = (r >> 6) * 64;
                float4 p = *(const float4*)(g_PA + r * 64 + dq + 4 * q);
                float4 o = *(const float4*)(g_COA + cb + dq + 4 * q);
                pa = make_float4(p.x + o.x, p.y + o.y, p.z + o.z, p.w + o.w);
                p = *(const float4*)(g_PB + r * 64 + dq + 4 * q);
                o = *(const float4*)(g_COB + cb + dq + 4 * q);
                pb = make_float4(p.x + o.x, p.y + o.y, p.z + o.z, p.w + o.w);
            }
            float4 ta = *(const float4*)(g_TA + dq + 4 * q);
            float4 res;
            res.x = c1 * (ta.x - pa.x) + c2 * pb.x;
            res.y = c1 * (ta.y - pa.y) + c2 * pb.y;
            res.z = c1 * (ta.z - pa.z) + c2 * pb.z;
            res.w = c1 * (ta.w - pa.w) + c2 * pb.w;
            res.x = res.x > 0.f ? res.x : expm1f(res.x);
            res.y = res.y > 0.f ? res.y : expm1f(res.y);
            res.z = res.z > 0.f ? res.z : expm1f(res.z);
            res.w = res.w > 0.f ? res.w : expm1f(res.w);
            *(float4*)(out + i * 64 + dq + 4 * q) = res;
        }
    }
}

// ---------------------------------------------------------------------------
extern "C" void kernel_launch(void* const* d_in, const int* in_sizes, int n_in,
                              void* d_out, int out_size) {
    const float* h = (const float*)d_in[0];
    const float* W = (const float*)d_in[1];
    const float* a = (const float*)d_in[2];
    float* out = (float*)d_out;

    k_all<<<NBLK, 256>>>(h, W, a, out);
}

// round 9
// speedup vs baseline: 10.9243x; 1.1770x over previous
#include <cuda_runtime.h>
#include <math.h>

#define NN    8192
#define NBLK  256
#define NCH   256      // chunks of 32 rows

// ---- scratch (device globals) ---------------------------------------------
__device__ float    g_Wh[NN * 64];
__device__ float    g_f1[NN], g_f2[NN];
__device__ unsigned g_keyR[NN];            // 32 locally-sorted runs of 256
__device__ unsigned g_key[NN];             // globally sorted keys
__device__ float4   g_ABs[NN];             // sorted: (A=e^f2, B=e^{.01 f2}, f2, 0)
__device__ float2   g_P[NN * 64];          // chunk-local prefix (PA, PB) interleaved
__device__ float2   g_CT[NCH * 64];        // chunk totals (A,B)
__device__ float2   g_CO[NCH * 64];        // chunk exclusive offsets
__device__ float    g_TA[64];
__device__ float2   g_PS[NN];              // chunk-local scalar prefixes (A,B)
__device__ float2   g_CS[NCH], g_COS[NCH];
__device__ float    g_totSA;
__device__ volatile unsigned g_barGen;     // zero-init
__device__ unsigned g_grpCnt[16 * 32];     // 16 groups, 128B apart, monotonic
__device__ unsigned g_topCnt;              // monotonic

__device__ __forceinline__ unsigned f2key(float f) {
    unsigned u = __float_as_uint(f);
    return (u & 0x80000000u) ? ~u : (u | 0x80000000u);
}

// Grid barrier: tree arrival (16 groups of 16, monotonic counters, no reset),
// volatile-load polling, plain-store release.
__device__ __forceinline__ void gsync() {
    __syncthreads();
    if (threadIdx.x == 0) {
        __threadfence();
        unsigned gen = g_barGen;
        bool rel = false;
        if ((atomicAdd(&g_grpCnt[(blockIdx.x >> 4) * 32], 1u) & 15u) == 15u) {
            if ((atomicAdd(&g_topCnt, 1u) & 15u) == 15u) {
                __threadfence();
                g_barGen = gen + 1;
                rel = true;
            }
        }
        if (!rel) while (g_barGen == gen) { }
        __threadfence();
    }
    __syncthreads();
}

__global__ void __launch_bounds__(256, 2) k_all(const float* __restrict__ h,
                                                const float* __restrict__ W,
                                                const float* __restrict__ a,
                                                float* __restrict__ out) {
    // 32 KB region reused: P1 W-tile -> P2 sort buf -> P3 staged keys (kept->P6)
    __shared__ union {
        float    sW[128 * 64];
        unsigned sk[256];
        unsigned keys[8192];
    } sm;
    __shared__ int    sj[32];
    __shared__ float2 sab[32];
    __shared__ float  segA[4][64], segB[4][64];
    __shared__ float  segSA[4], segSB[4];
    __shared__ float  sPSa[32], sPSb[32];
    __shared__ float2 sO[4][64];
    __shared__ float2 sscan[256];

    const int t = threadIdx.x, b = blockIdx.x;

    // ============ P1: Wh = h@W  (+ fused f1/f2), 32 rows/block ==============
    {
        for (int q = t; q < 4096; q += 256)
            ((float2*)sm.sW)[q] = ((const float2*)W)[q];
        __syncthreads();

        int d2 = t & 31, rs = t >> 5;
        int row0 = b * 32 + rs * 4;
        float2 a1v = *(const float2*)(a + 2 * d2);
        float2 a2v = *(const float2*)(a + 64 + 2 * d2);

        float2 acc[4];
        #pragma unroll
        for (int r = 0; r < 4; r++) acc[r] = make_float2(0.f, 0.f);

        #pragma unroll 4
        for (int kb = 0; kb < 32; kb++) {
            float2 w0 = *(const float2*)(sm.sW + (4 * kb + 0) * 64 + 2 * d2);
            float2 w1 = *(const float2*)(sm.sW + (4 * kb + 1) * 64 + 2 * d2);
            float2 w2 = *(const float2*)(sm.sW + (4 * kb + 2) * 64 + 2 * d2);
            float2 w3 = *(const float2*)(sm.sW + (4 * kb + 3) * 64 + 2 * d2);
            #pragma unroll
            for (int r = 0; r < 4; r++) {
                float4 hv = *(const float4*)(h + (row0 + r) * 128 + 4 * kb); // bcast
                acc[r].x += hv.x * w0.x + hv.y * w1.x + hv.z * w2.x + hv.w * w3.x;
                acc[r].y += hv.x * w0.y + hv.y * w1.y + hv.z * w2.y + hv.w * w3.y;
            }
        }
        #pragma unroll
        for (int r = 0; r < 4; r++)
            *(float2*)(g_Wh + (row0 + r) * 64 + 2 * d2) = acc[r];

        #pragma unroll
        for (int r = 0; r < 4; r++) {
            float p1 = acc[r].x * a1v.x + acc[r].y * a1v.y;
            float p2 = acc[r].x * a2v.x + acc[r].y * a2v.y;
            #pragma unroll
            for (int off = 16; off; off >>= 1) {
                p1 += __shfl_xor_sync(0xFFFFFFFFu, p1, off);
                p2 += __shfl_xor_sync(0xFFFFFFFFu, p2, off);
            }
            if (d2 == 0) { g_f1[row0 + r] = p1; g_f2[row0 + r] = p2; }
        }
    }
    gsync();

    // ============ P2: 32 blocks bitonic-sort 256 keys each ==================
    if (b < 32) {
        int base = b * 256;
        sm.sk[t] = (f2key(g_f2[base + t]) & 0xFFFFE000u) | (unsigned)(base + t);
        __syncthreads();
        #pragma unroll 1
        for (int k = 2; k <= 256; k <<= 1) {
            for (int j = k >> 1; j; j >>= 1) {
                int p = t ^ j;
                unsigned x = sm.sk[t], y = sm.sk[p];
                unsigned mn = min(x, y), mx = max(x, y);
                bool up = ((t & k) == 0);
                unsigned keep = ((t < p) == up) ? mn : mx;
                __syncthreads();
                sm.sk[t] = keep;
                __syncthreads();
            }
        }
        g_keyR[base + t] = sm.sk[t];
    }
    gsync();

    // ============ P3: rank-merge, runs staged in smem, 32 elems/block =======
    {
        for (int q = t; q < 2048; q += 256)
            ((uint4*)sm.keys)[q] = ((const uint4*)g_keyR)[q];
        __syncthreads();

        int e = b * 32 + (t >> 3), sub = t & 7;
        unsigned key = sm.keys[e];
        int own = e >> 8;
        int cnt = 0;
        #pragma unroll
        for (int r = sub * 4; r < sub * 4 + 4; r++) {
            if (r == own) continue;
            const unsigned* run = sm.keys + r * 256;
            int lo = 0, hi = 256;
            while (lo < hi) {
                int mid = (lo + hi) >> 1;
                if (run[mid] < key) lo = mid + 1; else hi = mid;
            }
            cnt += lo;
        }
        cnt += __shfl_xor_sync(0xFFFFFFFFu, cnt, 1);
        cnt += __shfl_xor_sync(0xFFFFFFFFu, cnt, 2);
        cnt += __shfl_xor_sync(0xFFFFFFFFu, cnt, 4);
        if (sub == 0) {
            int rank = (e & 255) + cnt;
            g_key[rank] = key;
            int j = key & 8191;
            float f2 = g_f2[j];
            g_ABs[rank] = make_float4(__expf(f2), __expf(0.01f * f2), f2, 0.f);
        }
    }
    gsync();

    // ============ P4: chunk-local prefix scans (block b = 32-row chunk b) ===
    {
        int d = t & 63, rg = t >> 6, r0 = b * 32;
        if (t < 32) {
            sj[t] = g_key[r0 + t] & 8191;
            float4 q4 = g_ABs[r0 + t];
            sab[t] = make_float2(q4.x, q4.y);
        }
        __syncthreads();

        float vA[8], vB[8];
        float accA = 0.f, accB = 0.f;
        #pragma unroll
        for (int q = 0; q < 8; q++) {
            int r = rg * 8 + q;
            float2 ab = sab[r];
            float wh = g_Wh[sj[r] * 64 + d];      // MLP=8 gathers
            accA += ab.x * wh;
            accB += ab.y * wh;
            vA[q] = accA; vB[q] = accB;
        }
        segA[rg][d] = accA;
        segB[rg][d] = accB;

        if (t < 4) {
            float sa = 0.f, sb = 0.f;
            #pragma unroll
            for (int q = 0; q < 8; q++) {
                float2 ab = sab[t * 8 + q];
                sa += ab.x; sb += ab.y;
                sPSa[t * 8 + q] = sa;
                sPSb[t * 8 + q] = sb;
            }
            segSA[t] = sa; segSB[t] = sb;
        }
        __syncthreads();

        float offA = 0.f, offB = 0.f;
        #pragma unroll
        for (int g = 0; g < 3; g++)
            if (g < rg) { offA += segA[g][d]; offB += segB[g][d]; }

        #pragma unroll
        for (int q = 0; q < 8; q++) {
            int r = r0 + rg * 8 + q;
            g_P[r * 64 + d] = make_float2(vA[q] + offA, vB[q] + offB);
        }
        if (rg == 3)
            g_CT[b * 64 + d] = make_float2(offA + accA, offB + accB);

        if (t < 4) {
            float oa = 0.f, ob = 0.f;
            for (int g = 0; g < t; g++) { oa += segSA[g]; ob += segSB[g]; }
            #pragma unroll
            for (int q = 0; q < 8; q++) {
                int r = r0 + t * 8 + q;
                g_PS[r] = make_float2(sPSa[t * 8 + q] + oa, sPSb[t * 8 + q] + ob);
            }
            if (t == 3)
                g_CS[b] = make_float2(oa + segSA[3], ob + segSB[3]);
        }
    }
    gsync();

    // ============ P5: chunk offsets (parallel) + scalar scan (block 0) ======
    {
        int d = t & 63, g = t >> 6;
        float2 o = make_float2(0.f, 0.f);
        for (int c = g; c < b; c += 4) {
            float2 v = g_CT[c * 64 + d];
            o.x += v.x; o.y += v.y;
        }
        sO[g][d] = o;
        __syncthreads();
        if (g == 0) {
            float2 A;
            A.x = sO[0][d].x + sO[1][d].x + sO[2][d].x + sO[3][d].x;
            A.y = sO[0][d].y + sO[1][d].y + sO[2][d].y + sO[3][d].y;
            g_CO[b * 64 + d] = A;
            if (b == NCH - 1) g_TA[d] = A.x + g_CT[(NCH - 1) * 64 + d].x;
        }
        if (b == 0) {
            sscan[t] = g_CS[t];
            __syncthreads();
            #pragma unroll 1
            for (int off = 1; off < 256; off <<= 1) {
                float2 v = sscan[t];
                float2 u = (t >= off) ? sscan[t - off] : make_float2(0.f, 0.f);
                __syncthreads();
                v.x += u.x; v.y += u.y;
                sscan[t] = v;
                __syncthreads();
            }
            float2 ex = t ? sscan[t - 1] : make_float2(0.f, 0.f);
            g_COS[t] = ex;
            if (t == 255) g_totSA = sscan[255].x;
        }
    }
    gsync();

    // ============ P6: threshold (LDS search on staged runs) + output ========
    {
        int e = t >> 3, sub = t & 7;
        int i = b * 32 + e;
        float f1 = g_f1[i];
        float maxf2 = g_ABs[NN - 1].z;
        float s0 = f1 + maxf2;
        float m  = fmaxf(s0, 0.01f * s0);
        float E1 = __expf(f1 - m);
        float E2 = __expf(0.01f * f1 - m);

        unsigned T = (f2key(-f1) & 0xFFFFE000u) | 0x1FFFu;
        int cnt = 0;
        #pragma unroll
        for (int r = sub * 4; r < sub * 4 + 4; r++) {
            const unsigned* run = sm.keys + r * 256;
            int lo = 0, hi = 256;
            while (lo < hi) {
                int mid = (lo + hi) >> 1;
                if (run[mid] <= T) lo = mid + 1; else hi = mid;
            }
            cnt += lo;
        }
        cnt += __shfl_xor_sync(0xFFFFFFFFu, cnt, 1);
        cnt += __shfl_xor_sync(0xFFFFFFFFu, cnt, 2);
        cnt += __shfl_xor_sync(0xFFFFFFFFu, cnt, 4);
        int k = cnt;

        float c1, c2;
        {
            float psa = 0.f, psb = 0.f;
            if (k > 0) {
                float2 ps = g_PS[k - 1];
                float2 co = g_COS[(k - 1) >> 5];
                psa = ps.x + co.x;
                psb = ps.y + co.y;
            }
            float inv = 1.0f / (E1 * (g_totSA - psa) + E2 * psb);
            c1 = E1 * inv; c2 = E2 * inv;
        }

        int dq = sub * 8;
        float res[8];
        const float4* pP = (const float4*)(g_P + (k > 0 ? (k - 1) * 64 : 0) + dq);
        const float4* pO = (const float4*)(g_CO + (k > 0 ? ((k - 1) >> 5) * 64 : 0) + dq);
        #pragma unroll
        for (int q = 0; q < 4; q++) {
            float4 pv = make_float4(0.f, 0.f, 0.f, 0.f), ov = pv;
            if (k > 0) { pv = pP[q]; ov = pO[q]; }
            // dims dq+2q, dq+2q+1 : (pa,pb) pairs
            float2 ta = *(const float2*)(g_TA + dq + 2 * q);
            float x0 = c1 * (ta.x - (pv.x + ov.x)) + c2 * (pv.y + ov.y);
            float x1 = c1 * (ta.y - (pv.z + ov.z)) + c2 * (pv.w + ov.w);
            res[2 * q]     = x0 > 0.f ? x0 : expm1f(x0);
            res[2 * q + 1] = x1 > 0.f ? x1 : expm1f(x1);
        }
        float4* o4 = (float4*)(out + i * 64 + dq);
        o4[0] = make_float4(res[0], res[1], res[2], res[3]);
        o4[1] = make_float4(res[4], res[5], res[6], res[7]);
    }
}

// ---------------------------------------------------------------------------
extern "C" void kernel_launch(void* const* d_in, const int* in_sizes, int n_in,
                              void* d_out, int out_size) {
    const float* h = (const float*)d_in[0];
    const float* W = (const float*)d_in[1];
    const float* a = (const float*)d_in[2];
    float* out = (float*)d_out;

    k_all<<<NBLK, 256>>>(h, W, a, out);
}